// round 13
// baseline (speedup 1.0000x reference)
#include <cuda_runtime.h>
#include <cuda_fp16.h>
#include <math.h>

// Fixed problem shape (per reference setup_inputs)
#define BB   2
#define NN   2048
#define CC   32
#define CP3  35          // C + 3
#define DD   32
#define DD2  1024        // D*D
#define BN   (BB*NN)     // 4096
#define KMAX 64
#define PTS  32          // points per prep tile

// Scratch (allocation-free rule: __device__ globals)
// A and c (both fp16) in "quad" layout per point:
// flat index (e>>2)*128 + d*4 + (e&3) for weight[d][e].
__device__ __align__(16) __half g_A[(size_t)BN * DD2];   // pre @ W_r1            (8 MB)
__device__ __align__(16) __half g_c[(size_t)BN * DD2];   // pre @ (W_r2-W_r1)+b_r (8 MB)
__device__ float g_v[BN * DD];            // relu(pre@W_v+b_v)
__device__ int   g_idx[BN * KMAX];        // flat neighbor indices (b*N+j)

// ---------------------------------------------------------------------------
// Kernel 1: exact KNN. One 11-bit-histogram pass + exact ranking of the
// boundary bucket (reproduces top_k smallest-index tie-break).
// one block per query point, 256 threads. Spread shared atomics.
// ---------------------------------------------------------------------------
__global__ void knn_kernel(const float* __restrict__ xyz,
                           const int* __restrict__ knnp,
                           int* __restrict__ idx_out)
{
    __shared__ unsigned s_u[NN];          // 8 KB: sortable keys
    __shared__ int      s_hist[2048];     // 8 KB: 11-bit histogram, reused as cand list
    __shared__ int      s_wsum[8];
    __shared__ int      s_bucket, s_less, s_cnt, s_c;

    const int g    = blockIdx.x;          // 0..BN-1
    const int base = (g / NN) * NN;       // batch base
    const int tid  = threadIdx.x;
    const int lane = tid & 31;
    const int w    = tid >> 5;
    const int K    = *knnp;
    const unsigned FULL = 0xFFFFFFFFu;

    const float xq = xyz[g*3+0], yq = xyz[g*3+1], zq = xyz[g*3+2];
    const float d2q = xq*xq + yq*yq + zq*zq;

    for (int i = tid; i < 2048; i += 256) s_hist[i] = 0;
    if (tid == 0) { s_cnt = 0; s_c = 0; }
    __syncthreads();

    // distances -> sortable uint keys + 11-bit histogram (spread atomics)
    for (int j = tid; j < NN; j += 256) {   // NN % 256 == 0: all lanes active
        const float x = xyz[(base+j)*3+0];
        const float y = xyz[(base+j)*3+1];
        const float z = xyz[(base+j)*3+2];
        const float d2j = x*x + y*y + z*z;
        const float dt  = x*xq + y*yq + z*zq;
        const float dist = (d2q + d2j) - 2.0f * dt;   // reference formula
        const unsigned bits = __float_as_uint(dist);
        const unsigned u = (bits & 0x80000000u) ? ~bits : (bits | 0x80000000u);
        s_u[j] = u;
        atomicAdd(&s_hist[u >> 21], 1);
    }
    __syncthreads();

    // find bucket containing rank K: thread t owns bins [8t, 8t+8)
    const int lo = tid * 8;
    int h[8]; int lsum = 0;
    #pragma unroll
    for (int i = 0; i < 8; ++i) { h[i] = s_hist[lo + i]; lsum += h[i]; }
    int incl = lsum;
    #pragma unroll
    for (int o = 1; o < 32; o <<= 1) {
        const int v = __shfl_up_sync(FULL, incl, o);
        if (lane >= o) incl += v;
    }
    if (lane == 31) s_wsum[w] = incl;
    __syncthreads();
    int woff = 0;
    #pragma unroll
    for (int i = 0; i < 8; ++i) if (i < w) woff += s_wsum[i];
    const int texcl = woff + incl - lsum;      // exclusive prefix for this thread's bins
    if (texcl < K && K <= woff + incl) {
        int cum = texcl;
        #pragma unroll
        for (int i = 0; i < 8; ++i) {
            if (cum + h[i] >= K) { s_bucket = lo + i; s_less = cum; break; }
            cum += h[i];
        }
    }
    __syncthreads();
    const unsigned B  = (unsigned)s_bucket;
    const int less    = s_less;
    const int rneed   = K - less;
    int* s_cand = s_hist;                     // histogram no longer needed

    // emit all strictly-smaller buckets (order-free, sparse predicate ->
    // plain atomics), compact boundary bucket candidates
    for (int j = tid; j < NN; j += 256) {
        const unsigned u = s_u[j];
        const unsigned bk = u >> 21;
        if (bk < B) {
            const int p = atomicAdd(&s_cnt, 1);
            idx_out[(size_t)g*KMAX + p] = base + j;
        } else if (bk == B) {
            const int p = atomicAdd(&s_c, 1);
            s_cand[p] = j;
        }
    }
    __syncthreads();

    // exact rank (value, then index) within boundary bucket -> positions [less, K)
    const int c = s_c;
    for (int ci = tid; ci < c; ci += 256) {
        const int j = s_cand[ci];
        const unsigned u = s_u[j];
        int rank = 0;
        for (int i = 0; i < c; ++i) {
            const int ji = s_cand[i];
            const unsigned ui = s_u[ji];
            rank += (ui < u) || (ui == u && ji < j);
        }
        if (rank < rneed)
            idx_out[(size_t)g*KMAX + less + rank] = base + j;
    }
}

// ---------------------------------------------------------------------------
// Kernel 2: A = pre @ W_r1 ; c = pre @ (W_r2 - W_r1) + b_r  (fp32 accumulate,
// fp16 store, quad layout). + fused v = relu(pre @ W_v + b_v) on y==0 blocks.
// tile 32 points x 128 cols, 256 threads, 4pt x 4col per thread
// ---------------------------------------------------------------------------
__global__ void prep_kernel(const float* __restrict__ feature,
                            const float* __restrict__ xyz,
                            const float* __restrict__ W_r,
                            const float* __restrict__ b_r,
                            const float* __restrict__ W_v,
                            const float* __restrict__ b_v)
{
    __shared__ float s_pre[PTS][CP3 + 1];
    __shared__ float s_w1[CP3][128];
    __shared__ float s_wd[CP3][128];

    const int p0  = blockIdx.x * PTS;
    const int c0  = blockIdx.y * 128;
    const int tid = threadIdx.x;

    for (int t = tid; t < PTS * CP3; t += 256) {
        const int p = t / CP3, i = t % CP3;
        const int gg = p0 + p;
        s_pre[p][i] = (i < CC) ? feature[(size_t)gg*CC + i] : xyz[(size_t)gg*3 + (i - CC)];
    }
    for (int t = tid; t < CP3 * 128; t += 256) {
        const int i = t >> 7, cc = t & 127;
        const float w1 = W_r[(size_t)i*DD2 + c0 + cc];
        const float w2 = W_r[(size_t)(CP3 + i)*DD2 + c0 + cc];
        s_w1[i][cc] = w1;
        s_wd[i][cc] = w2 - w1;
    }
    __syncthreads();

    const int cq  = tid & 31;        // col group (4 cols)
    const int prg = tid >> 5;        // point group: points prg + pp*8
    const int cb  = cq * 4;

    float accA[4][4] = {};
    float accC[4][4] = {};

    for (int i = 0; i < CP3; ++i) {
        const float4 w1 = *reinterpret_cast<const float4*>(&s_w1[i][cb]);
        const float4 wd = *reinterpret_cast<const float4*>(&s_wd[i][cb]);
        #pragma unroll
        for (int pp = 0; pp < 4; ++pp) {
            const float pv = s_pre[prg + pp*8][i];   // warp-uniform -> broadcast
            accA[pp][0] = fmaf(pv, w1.x, accA[pp][0]);
            accA[pp][1] = fmaf(pv, w1.y, accA[pp][1]);
            accA[pp][2] = fmaf(pv, w1.z, accA[pp][2]);
            accA[pp][3] = fmaf(pv, w1.w, accA[pp][3]);
            accC[pp][0] = fmaf(pv, wd.x, accC[pp][0]);
            accC[pp][1] = fmaf(pv, wd.y, accC[pp][1]);
            accC[pp][2] = fmaf(pv, wd.z, accC[pp][2]);
            accC[pp][3] = fmaf(pv, wd.w, accC[pp][3]);
        }
    }

    // quad-layout destination: col = d*32 + e ; flat_q = (e>>2)*128 + d*4 + (e&3)
    const int col0  = c0 + cb;              // multiple of 4
    const int dRow  = col0 >> 5;
    const int eBase = col0 & 31;            // multiple of 4
    const int qoff  = (eBase >> 2) * 128 + dRow * 4;

    const float br0 = __ldg(b_r + col0 + 0), br1 = __ldg(b_r + col0 + 1);
    const float br2 = __ldg(b_r + col0 + 2), br3 = __ldg(b_r + col0 + 3);

    #pragma unroll
    for (int pp = 0; pp < 4; ++pp) {
        const int gg = p0 + prg + pp * 8;
        const size_t off = (size_t)gg * DD2 + qoff;
        *reinterpret_cast<__half2*>(&g_A[off])     = __floats2half2_rn(accA[pp][0], accA[pp][1]);
        *reinterpret_cast<__half2*>(&g_A[off + 2]) = __floats2half2_rn(accA[pp][2], accA[pp][3]);
        *reinterpret_cast<__half2*>(&g_c[off])     = __floats2half2_rn(accC[pp][0] + br0, accC[pp][1] + br1);
        *reinterpret_cast<__half2*>(&g_c[off + 2]) = __floats2half2_rn(accC[pp][2] + br2, accC[pp][3] + br3);
    }

    // fused v = relu(pre @ W_v + b_v) using the staged s_pre
    if (blockIdx.y == 0) {
        for (int t = tid; t < PTS * DD; t += 256) {
            const int p = t >> 5, d = t & 31;
            float acc = __ldg(b_v + d);
            #pragma unroll 7
            for (int i = 0; i < CP3; ++i)
                acc = fmaf(s_pre[p][i], __ldg(W_v + i*DD + d), acc);
            g_v[(size_t)(p0 + p)*DD + d] = fmaxf(acc, 0.0f);
        }
    }
}

// ---------------------------------------------------------------------------
// Kernel 3: main aggregation, split-row half2 pipeline, depth-1 prefetch,
// fused tail write.
// ---------------------------------------------------------------------------
#define EPI_PITCH 33
__global__ void __launch_bounds__(256)
main_kernel(const int* __restrict__ knnp,
            const float* __restrict__ W_s,
            const float* __restrict__ b_s,
            float* __restrict__ out,
            int tailpos)
{
    __shared__ float s_acc[8][16][EPI_PITCH];   // 16.5 KB, per-warp regions

    const int tid   = threadIdx.x;
    const int lane  = tid & 31;
    const int w     = tid >> 5;
    const int pw    = w >> 2;             // point within block (0/1)
    const int wq    = w & 3;              // warp within point
    const int unit  = wq >> 1;            // k-parity unit (0/1)
    const int dhalf = wq & 1;             // which 16 rows
    const int dp    = lane & 15;
    const int eh    = lane >> 4;          // which 16 cols
    const int d     = dhalf * 16 + dp;
    const int g     = blockIdx.x * 2 + pw;
    const int K     = *knnp;

    if (tailpos >= 0 && blockIdx.x == 0 && tid == 255)
        out[tailpos] = (float)NN;

    // zero own region
    for (int i = lane; i < 16 * EPI_PITCH; i += 32)
        (&s_acc[w][0][0])[i] = 0.0f;
    __syncwarp();

    // c half-row: quads eq = eh*4 + q, uint2 index = eq*32 + d
    const uint2* __restrict__ Cq = reinterpret_cast<const uint2*>(g_c + (size_t)g * DD2);
    __half2 ch[8];
    #pragma unroll
    for (int q = 0; q < 4; ++q) {
        const uint2 cr = Cq[(eh*4 + q)*32 + d];
        ch[2*q]   = *reinterpret_cast<const __half2*>(&cr.x);
        ch[2*q+1] = *reinterpret_cast<const __half2*>(&cr.y);
    }

    const int* __restrict__ idxp = g_idx + (size_t)g * KMAX;
    const float SQRTD = 5.656854249492381f;   // sqrt(32)
    const __half2 HZ = __float2half2_rn(0.0f);
    const int qbase = eh * 4;

    int k = unit;
    uint2 r[4];
    float gvv = 0.0f;
    if (k < K) {
        const int m = __ldg(idxp + k);
        const uint2* __restrict__ Aq =
            reinterpret_cast<const uint2*>(g_A + (size_t)m * DD2);
        #pragma unroll
        for (int q = 0; q < 4; ++q) r[q] = Aq[(qbase + q)*32 + d];
        gvv = __ldg(g_v + (size_t)m*DD + d);
    }

    #pragma unroll 1
    while (k < K) {
        __half2 hacc[8];
        #pragma unroll
        for (int i = 0; i < 8; ++i) hacc[i] = HZ;

        #pragma unroll 1
        for (int t = 0; t < 3 && k < K; ++t) {
            // compute x for current k from prefetched regs
            __half2 xh[8];
            __half2 rsh = HZ;
            #pragma unroll
            for (int q = 0; q < 4; ++q) {
                const __half2 a0 = *reinterpret_cast<const __half2*>(&r[q].x);
                const __half2 a1 = *reinterpret_cast<const __half2*>(&r[q].y);
                xh[2*q]   = __hadd2(a0, ch[2*q]);
                xh[2*q+1] = __hadd2(a1, ch[2*q+1]);
                rsh = __hadd2(rsh, __habs2(xh[2*q]));
                rsh = __hadd2(rsh, __habs2(xh[2*q+1]));
            }

            // prefetch k+2 while the reduction chain drains
            const int kn = k + 2;
            uint2 rn[4];
            float gvn = 0.0f;
            if (kn < K) {
                const int mn = __ldg(idxp + kn);
                const uint2* __restrict__ Aqn =
                    reinterpret_cast<const uint2*>(g_A + (size_t)mn * DD2);
                #pragma unroll
                for (int q = 0; q < 4; ++q) rn[q] = Aqn[(qbase + q)*32 + d];
                gvn = __ldg(g_v + (size_t)mn*DD + d);
            }

            const float2 fr = __half22float2(rsh);
            float rs = fr.x + fr.y;
            rs += __shfl_xor_sync(0xFFFFFFFFu, rs, 16);     // full row sum
            const float coef = gvv * __fdividef(SQRTD, rs + 3.2e-6f);  // + D*1e-7
            const __half2 c2 = __float2half2_rn(coef);

            #pragma unroll
            for (int i = 0; i < 8; ++i)
                hacc[i] = __hfma2(c2, xh[i], hacc[i]);

            #pragma unroll
            for (int q = 0; q < 4; ++q) r[q] = rn[q];
            gvv = gvn;
            k = kn;
        }

        // flush half partials into per-warp smem region (conflict-free)
        #pragma unroll
        for (int i = 0; i < 8; ++i) {
            const float2 f = __half22float2(hacc[i]);
            const int e0 = eh*16 + (i >> 1)*4 + (i & 1)*2;
            s_acc[w][dp][e0]     += f.x;
            s_acc[w][dp][e0 + 1] += f.y;
        }
    }
    __syncthreads();

    // epilogue: sum the point's 4 warp regions over all 16 d' rows, then W_s
    if (wq == 0) {
        const int b0 = pw * 4;
        float tot = 0.0f;
        #pragma unroll
        for (int dd = 0; dd < 16; ++dd)
            tot += (s_acc[b0][dd][lane]   + s_acc[b0+1][dd][lane])
                 + (s_acc[b0+2][dd][lane] + s_acc[b0+3][dd][lane]);
        float o2 = b_s[lane];
        #pragma unroll
        for (int e = 0; e < DD; ++e) {
            const float te = __shfl_sync(0xFFFFFFFFu, tot, e);
            o2 = fmaf(te, W_s[e*DD + lane], o2);
        }
        out[(size_t)g*DD + lane] = o2;
    }
}

// ---------------------------------------------------------------------------
// Side stream + events for graph-forked knn/prep overlap (kept from R11).
// ---------------------------------------------------------------------------
static cudaStream_t g_s1 = nullptr;
static cudaEvent_t  g_evFork = nullptr, g_evJoin = nullptr;

extern "C" void kernel_launch(void* const* d_in, const int* in_sizes, int n_in,
                              void* d_out, int out_size)
{
    const float* feature = (const float*)d_in[0];
    const float* xyz     = (const float*)d_in[1];
    const float* W_r     = (const float*)d_in[2];
    const float* b_r     = (const float*)d_in[3];
    const float* W_v     = (const float*)d_in[4];
    const float* b_v     = (const float*)d_in[5];
    const float* W_s     = (const float*)d_in[6];
    const float* b_s     = (const float*)d_in[7];
    const int*   knnp    = (const int*)d_in[8];
    float* out = (float*)d_out;

    int* idx_out;
    cudaGetSymbolAddress((void**)&idx_out, g_idx);  // host-side address query (no alloc)

    if (g_s1 == nullptr) {
        cudaStreamCreateWithFlags(&g_s1, cudaStreamNonBlocking);
        cudaEventCreateWithFlags(&g_evFork, cudaEventDisableTiming);
        cudaEventCreateWithFlags(&g_evJoin, cudaEventDisableTiming);
    }

    // fork: knn on side stream, prep on main stream (independent)
    cudaEventRecord(g_evFork, 0);
    cudaStreamWaitEvent(g_s1, g_evFork, 0);
    knn_kernel<<<BN, 256, 0, g_s1>>>(xyz, knnp, idx_out);
    prep_kernel<<<dim3(BN/PTS, DD2/128), 256>>>(feature, xyz, W_r, b_r, W_v, b_v);
    // join: main needs both
    cudaEventRecord(g_evJoin, g_s1);
    cudaStreamWaitEvent(0, g_evJoin, 0);

    const int total = BN * DD;
    const int tailpos = (out_size > total) ? total : -1;
    main_kernel<<<BN/2, 256>>>(knnp, W_s, b_s, out, tailpos);
}

// round 14
// speedup vs baseline: 1.0664x; 1.0664x over previous
#include <cuda_runtime.h>
#include <cuda_fp16.h>
#include <math.h>

// Fixed problem shape (per reference setup_inputs)
#define BB   2
#define NN   2048
#define CC   32
#define CP3  35          // C + 3
#define DD   32
#define DD2  1024        // D*D
#define BN   (BB*NN)     // 4096
#define KMAX 64
#define PTS  32          // points per prep tile

// Scratch (allocation-free rule: __device__ globals)
// A and c (both fp16) in "quad" layout per point:
// flat index (e>>2)*128 + d*4 + (e&3) for weight[d][e].
__device__ __align__(16) __half g_A[(size_t)BN * DD2];   // pre @ W_r1            (8 MB)
__device__ __align__(16) __half g_c[(size_t)BN * DD2];   // pre @ (W_r2-W_r1)+b_r (8 MB)
__device__ float g_v[BN * DD];            // relu(pre@W_v+b_v)
__device__ int   g_idx[BN * KMAX];        // flat neighbor indices (b*N+j)
__device__ __align__(16) float4 g_xyz4[BN];  // packed (x, y, z, |p|^2)

// ---------------------------------------------------------------------------
// Kernel 0: pack xyz into float4 with precomputed squared norm
// ---------------------------------------------------------------------------
__global__ void pack_kernel(const float* __restrict__ xyz)
{
    const int i = blockIdx.x * 256 + threadIdx.x;
    if (i < BN) {
        const float x = xyz[i*3+0], y = xyz[i*3+1], z = xyz[i*3+2];
        g_xyz4[i] = make_float4(x, y, z, x*x + y*y + z*z);
    }
}

// ---------------------------------------------------------------------------
// Kernel 1: exact KNN. One 11-bit-histogram pass + exact ranking of the
// boundary bucket (reproduces top_k smallest-index tie-break).
// one block per query point, 256 threads. Spread shared atomics.
// ---------------------------------------------------------------------------
__global__ void knn_kernel(const int* __restrict__ knnp,
                           int* __restrict__ idx_out)
{
    __shared__ unsigned s_u[NN];          // 8 KB: sortable keys
    __shared__ int      s_hist[2048];     // 8 KB: 11-bit histogram, reused as cand list
    __shared__ int      s_wsum[8];
    __shared__ int      s_bucket, s_less, s_cnt, s_c;

    const int g    = blockIdx.x;          // 0..BN-1
    const int base = (g / NN) * NN;       // batch base
    const int tid  = threadIdx.x;
    const int lane = tid & 31;
    const int w    = tid >> 5;
    const int K    = *knnp;
    const unsigned FULL = 0xFFFFFFFFu;

    const float4 q = g_xyz4[g];
    const float xq = q.x, yq = q.y, zq = q.z, d2q = q.w;

    for (int i = tid; i < 2048; i += 256) s_hist[i] = 0;
    if (tid == 0) { s_cnt = 0; s_c = 0; }
    __syncthreads();

    // distances -> sortable uint keys + 11-bit histogram (spread atomics)
    for (int j = tid; j < NN; j += 256) {   // NN % 256 == 0: all lanes active
        const float4 p = g_xyz4[base + j];
        const float dt = fmaf(p.x, xq, fmaf(p.y, yq, p.z * zq));
        const float dist = (d2q + p.w) - 2.0f * dt;   // reference formula
        const unsigned bits = __float_as_uint(dist);
        const unsigned u = (bits & 0x80000000u) ? ~bits : (bits | 0x80000000u);
        s_u[j] = u;
        atomicAdd(&s_hist[u >> 21], 1);
    }
    __syncthreads();

    // find bucket containing rank K: thread t owns bins [8t, 8t+8)
    const int lo = tid * 8;
    int h[8]; int lsum = 0;
    #pragma unroll
    for (int i = 0; i < 8; ++i) { h[i] = s_hist[lo + i]; lsum += h[i]; }
    int incl = lsum;
    #pragma unroll
    for (int o = 1; o < 32; o <<= 1) {
        const int v = __shfl_up_sync(FULL, incl, o);
        if (lane >= o) incl += v;
    }
    if (lane == 31) s_wsum[w] = incl;
    __syncthreads();
    int woff = 0;
    #pragma unroll
    for (int i = 0; i < 8; ++i) if (i < w) woff += s_wsum[i];
    const int texcl = woff + incl - lsum;      // exclusive prefix for this thread's bins
    if (texcl < K && K <= woff + incl) {
        int cum = texcl;
        #pragma unroll
        for (int i = 0; i < 8; ++i) {
            if (cum + h[i] >= K) { s_bucket = lo + i; s_less = cum; break; }
            cum += h[i];
        }
    }
    __syncthreads();
    const unsigned B  = (unsigned)s_bucket;
    const int less    = s_less;
    const int rneed   = K - less;
    int* s_cand = s_hist;                     // histogram no longer needed

    // emit all strictly-smaller buckets (order-free, sparse predicate ->
    // plain atomics), compact boundary bucket candidates
    for (int j = tid; j < NN; j += 256) {
        const unsigned u = s_u[j];
        const unsigned bk = u >> 21;
        if (bk < B) {
            const int p = atomicAdd(&s_cnt, 1);
            idx_out[(size_t)g*KMAX + p] = base + j;
        } else if (bk == B) {
            const int p = atomicAdd(&s_c, 1);
            s_cand[p] = j;
        }
    }
    __syncthreads();

    // exact rank (value, then index) within boundary bucket -> positions [less, K)
    const int c = s_c;
    for (int ci = tid; ci < c; ci += 256) {
        const int j = s_cand[ci];
        const unsigned u = s_u[j];
        int rank = 0;
        for (int i = 0; i < c; ++i) {
            const int ji = s_cand[i];
            const unsigned ui = s_u[ji];
            rank += (ui < u) || (ui == u && ji < j);
        }
        if (rank < rneed)
            idx_out[(size_t)g*KMAX + less + rank] = base + j;
    }
}

// ---------------------------------------------------------------------------
// Kernel 2: A = pre @ W_r1 ; c = pre @ (W_r2 - W_r1) + b_r  (fp32 accumulate,
// fp16 store, quad layout). + fused v = relu(pre @ W_v + b_v) on y==0 blocks.
// tile 32 points x 128 cols, 256 threads, 4pt x 4col per thread
// ---------------------------------------------------------------------------
__global__ void prep_kernel(const float* __restrict__ feature,
                            const float* __restrict__ xyz,
                            const float* __restrict__ W_r,
                            const float* __restrict__ b_r,
                            const float* __restrict__ W_v,
                            const float* __restrict__ b_v)
{
    __shared__ float s_pre[PTS][CP3 + 1];
    __shared__ float s_w1[CP3][128];
    __shared__ float s_wd[CP3][128];

    const int p0  = blockIdx.x * PTS;
    const int c0  = blockIdx.y * 128;
    const int tid = threadIdx.x;

    for (int t = tid; t < PTS * CP3; t += 256) {
        const int p = t / CP3, i = t % CP3;
        const int gg = p0 + p;
        s_pre[p][i] = (i < CC) ? feature[(size_t)gg*CC + i] : xyz[(size_t)gg*3 + (i - CC)];
    }
    for (int t = tid; t < CP3 * 128; t += 256) {
        const int i = t >> 7, cc = t & 127;
        const float w1 = W_r[(size_t)i*DD2 + c0 + cc];
        const float w2 = W_r[(size_t)(CP3 + i)*DD2 + c0 + cc];
        s_w1[i][cc] = w1;
        s_wd[i][cc] = w2 - w1;
    }
    __syncthreads();

    const int cq  = tid & 31;        // col group (4 cols)
    const int prg = tid >> 5;        // point group: points prg + pp*8
    const int cb  = cq * 4;

    float accA[4][4] = {};
    float accC[4][4] = {};

    for (int i = 0; i < CP3; ++i) {
        const float4 w1 = *reinterpret_cast<const float4*>(&s_w1[i][cb]);
        const float4 wd = *reinterpret_cast<const float4*>(&s_wd[i][cb]);
        #pragma unroll
        for (int pp = 0; pp < 4; ++pp) {
            const float pv = s_pre[prg + pp*8][i];   // warp-uniform -> broadcast
            accA[pp][0] = fmaf(pv, w1.x, accA[pp][0]);
            accA[pp][1] = fmaf(pv, w1.y, accA[pp][1]);
            accA[pp][2] = fmaf(pv, w1.z, accA[pp][2]);
            accA[pp][3] = fmaf(pv, w1.w, accA[pp][3]);
            accC[pp][0] = fmaf(pv, wd.x, accC[pp][0]);
            accC[pp][1] = fmaf(pv, wd.y, accC[pp][1]);
            accC[pp][2] = fmaf(pv, wd.z, accC[pp][2]);
            accC[pp][3] = fmaf(pv, wd.w, accC[pp][3]);
        }
    }

    // quad-layout destination: col = d*32 + e ; flat_q = (e>>2)*128 + d*4 + (e&3)
    const int col0  = c0 + cb;              // multiple of 4
    const int dRow  = col0 >> 5;
    const int eBase = col0 & 31;            // multiple of 4
    const int qoff  = (eBase >> 2) * 128 + dRow * 4;

    const float br0 = __ldg(b_r + col0 + 0), br1 = __ldg(b_r + col0 + 1);
    const float br2 = __ldg(b_r + col0 + 2), br3 = __ldg(b_r + col0 + 3);

    #pragma unroll
    for (int pp = 0; pp < 4; ++pp) {
        const int gg = p0 + prg + pp * 8;
        const size_t off = (size_t)gg * DD2 + qoff;
        *reinterpret_cast<__half2*>(&g_A[off])     = __floats2half2_rn(accA[pp][0], accA[pp][1]);
        *reinterpret_cast<__half2*>(&g_A[off + 2]) = __floats2half2_rn(accA[pp][2], accA[pp][3]);
        *reinterpret_cast<__half2*>(&g_c[off])     = __floats2half2_rn(accC[pp][0] + br0, accC[pp][1] + br1);
        *reinterpret_cast<__half2*>(&g_c[off + 2]) = __floats2half2_rn(accC[pp][2] + br2, accC[pp][3] + br3);
    }

    // fused v = relu(pre @ W_v + b_v) using the staged s_pre
    if (blockIdx.y == 0) {
        for (int t = tid; t < PTS * DD; t += 256) {
            const int p = t >> 5, d = t & 31;
            float acc = __ldg(b_v + d);
            #pragma unroll 7
            for (int i = 0; i < CP3; ++i)
                acc = fmaf(s_pre[p][i], __ldg(W_v + i*DD + d), acc);
            g_v[(size_t)(p0 + p)*DD + d] = fmaxf(acc, 0.0f);
        }
    }
}

// ---------------------------------------------------------------------------
// Kernel 3: main aggregation, split-row half2 pipeline (R11 form, no
// prefetch), fused tail write.
// ---------------------------------------------------------------------------
#define EPI_PITCH 33
__global__ void __launch_bounds__(256)
main_kernel(const int* __restrict__ knnp,
            const float* __restrict__ W_s,
            const float* __restrict__ b_s,
            float* __restrict__ out,
            int tailpos)
{
    __shared__ float s_acc[8][16][EPI_PITCH];   // 16.5 KB, per-warp regions

    const int tid   = threadIdx.x;
    const int lane  = tid & 31;
    const int w     = tid >> 5;
    const int pw    = w >> 2;             // point within block (0/1)
    const int wq    = w & 3;              // warp within point
    const int unit  = wq >> 1;            // k-parity unit (0/1)
    const int dhalf = wq & 1;             // which 16 rows
    const int dp    = lane & 15;
    const int eh    = lane >> 4;          // which 16 cols
    const int d     = dhalf * 16 + dp;
    const int g     = blockIdx.x * 2 + pw;
    const int K     = *knnp;

    if (tailpos >= 0 && blockIdx.x == 0 && tid == 255)
        out[tailpos] = (float)NN;

    // zero own region
    for (int i = lane; i < 16 * EPI_PITCH; i += 32)
        (&s_acc[w][0][0])[i] = 0.0f;
    __syncwarp();

    // c half-row: quads eq = eh*4 + q, uint2 index = eq*32 + d
    const uint2* __restrict__ Cq = reinterpret_cast<const uint2*>(g_c + (size_t)g * DD2);
    __half2 ch[8];
    #pragma unroll
    for (int q = 0; q < 4; ++q) {
        const uint2 cr = Cq[(eh*4 + q)*32 + d];
        ch[2*q]   = *reinterpret_cast<const __half2*>(&cr.x);
        ch[2*q+1] = *reinterpret_cast<const __half2*>(&cr.y);
    }

    const int* __restrict__ idxp = g_idx + (size_t)g * KMAX;
    const float SQRTD = 5.656854249492381f;   // sqrt(32)
    const __half2 HZ = __float2half2_rn(0.0f);

    int k = unit;
    #pragma unroll 1
    while (k < K) {
        __half2 hacc[8];
        #pragma unroll
        for (int i = 0; i < 8; ++i) hacc[i] = HZ;

        #pragma unroll 1
        for (int t = 0; t < 3 && k < K; ++t, k += 2) {
            const int m = __ldg(idxp + k);
            const uint2* __restrict__ Aq =
                reinterpret_cast<const uint2*>(g_A + (size_t)m * DD2);
            const float gvv = __ldg(g_v + (size_t)m*DD + d);

            uint2 r[4];
            #pragma unroll
            for (int q = 0; q < 4; ++q) r[q] = Aq[(eh*4 + q)*32 + d];

            __half2 xh[8];
            __half2 rsh = HZ;
            #pragma unroll
            for (int q = 0; q < 4; ++q) {
                const __half2 a0 = *reinterpret_cast<const __half2*>(&r[q].x);
                const __half2 a1 = *reinterpret_cast<const __half2*>(&r[q].y);
                xh[2*q]   = __hadd2(a0, ch[2*q]);
                xh[2*q+1] = __hadd2(a1, ch[2*q+1]);
                rsh = __hadd2(rsh, __habs2(xh[2*q]));
                rsh = __hadd2(rsh, __habs2(xh[2*q+1]));
            }
            const float2 fr = __half22float2(rsh);
            float rs = fr.x + fr.y;
            rs += __shfl_xor_sync(0xFFFFFFFFu, rs, 16);     // full row sum
            const float coef = gvv * __fdividef(SQRTD, rs + 3.2e-6f);  // + D*1e-7
            const __half2 c2 = __float2half2_rn(coef);

            #pragma unroll
            for (int i = 0; i < 8; ++i)
                hacc[i] = __hfma2(c2, xh[i], hacc[i]);
        }

        // flush half partials into per-warp smem region (conflict-free)
        #pragma unroll
        for (int i = 0; i < 8; ++i) {
            const float2 f = __half22float2(hacc[i]);
            const int e0 = eh*16 + (i >> 1)*4 + (i & 1)*2;
            s_acc[w][dp][e0]     += f.x;
            s_acc[w][dp][e0 + 1] += f.y;
        }
    }
    __syncthreads();

    // epilogue: sum the point's 4 warp regions over all 16 d' rows, then W_s
    if (wq == 0) {
        const int b0 = pw * 4;
        float tot = 0.0f;
        #pragma unroll
        for (int dd = 0; dd < 16; ++dd)
            tot += (s_acc[b0][dd][lane]   + s_acc[b0+1][dd][lane])
                 + (s_acc[b0+2][dd][lane] + s_acc[b0+3][dd][lane]);
        float o2 = b_s[lane];
        #pragma unroll
        for (int e = 0; e < DD; ++e) {
            const float te = __shfl_sync(0xFFFFFFFFu, tot, e);
            o2 = fmaf(te, W_s[e*DD + lane], o2);
        }
        out[(size_t)g*DD + lane] = o2;
    }
}

// ---------------------------------------------------------------------------
// Side stream + events for graph-forked knn/prep overlap.
// ---------------------------------------------------------------------------
static cudaStream_t g_s1 = nullptr;
static cudaEvent_t  g_evFork = nullptr, g_evJoin = nullptr;

extern "C" void kernel_launch(void* const* d_in, const int* in_sizes, int n_in,
                              void* d_out, int out_size)
{
    const float* feature = (const float*)d_in[0];
    const float* xyz     = (const float*)d_in[1];
    const float* W_r     = (const float*)d_in[2];
    const float* b_r     = (const float*)d_in[3];
    const float* W_v     = (const float*)d_in[4];
    const float* b_v     = (const float*)d_in[5];
    const float* W_s     = (const float*)d_in[6];
    const float* b_s     = (const float*)d_in[7];
    const int*   knnp    = (const int*)d_in[8];
    float* out = (float*)d_out;

    int* idx_out;
    cudaGetSymbolAddress((void**)&idx_out, g_idx);  // host-side address query (no alloc)

    if (g_s1 == nullptr) {
        cudaStreamCreateWithFlags(&g_s1, cudaStreamNonBlocking);
        cudaEventCreateWithFlags(&g_evFork, cudaEventDisableTiming);
        cudaEventCreateWithFlags(&g_evJoin, cudaEventDisableTiming);
    }

    // pack xyz (+|p|^2) first; knn (side stream) depends on it via fork event
    pack_kernel<<<(BN + 255)/256, 256>>>(xyz);
    cudaEventRecord(g_evFork, 0);
    cudaStreamWaitEvent(g_s1, g_evFork, 0);
    knn_kernel<<<BN, 256, 0, g_s1>>>(knnp, idx_out);
    prep_kernel<<<dim3(BN/PTS, DD2/128), 256>>>(feature, xyz, W_r, b_r, W_v, b_v);
    // join: main needs both
    cudaEventRecord(g_evJoin, g_s1);
    cudaStreamWaitEvent(0, g_evJoin, 0);

    const int total = BN * DD;
    const int tailpos = (out_size > total) ? total : -1;
    main_kernel<<<BN/2, 256>>>(knnp, W_s, b_s, out, tailpos);
}

// round 16
// speedup vs baseline: 1.0888x; 1.0210x over previous
#include <cuda_runtime.h>
#include <cuda_fp16.h>
#include <math.h>

// Fixed problem shape (per reference setup_inputs)
#define BB   2
#define NN   2048
#define CC   32
#define CP3  35          // C + 3
#define DD   32
#define DD2  1024        // D*D
#define BN   (BB*NN)     // 4096
#define KMAX 64
#define PTS  32          // points per prep tile

// Scratch (allocation-free rule: __device__ globals)
// A and c (both fp16) in "oct" layout per point:
// flat index (e>>3)*256 + d*8 + (e&7) for weight[d][e]; a thread (lane = eh*16+dp,
// owning d and e in [eh*16, eh*16+16)) reads its half-row as two uint4s at
// uint4-index (eh*2+q)*32 + d  (q = 0,1) — fully coalesced 512 B per warp load.
__device__ __align__(16) __half g_A[(size_t)BN * DD2];   // pre @ W_r1            (8 MB)
__device__ __align__(16) __half g_c[(size_t)BN * DD2];   // pre @ (W_r2-W_r1)+b_r (8 MB)
__device__ float g_v[BN * DD];            // relu(pre@W_v+b_v)
__device__ int   g_idx[BN * KMAX];        // flat neighbor indices (b*N+j)
__device__ __align__(16) float4 g_xyz4[BN];  // packed (x, y, z, |p|^2)

// ---------------------------------------------------------------------------
// Kernel 0: pack xyz into float4 with precomputed squared norm
// ---------------------------------------------------------------------------
__global__ void pack_kernel(const float* __restrict__ xyz)
{
    const int i = blockIdx.x * 256 + threadIdx.x;
    if (i < BN) {
        const float x = xyz[i*3+0], y = xyz[i*3+1], z = xyz[i*3+2];
        g_xyz4[i] = make_float4(x, y, z, x*x + y*y + z*z);
    }
}

// ---------------------------------------------------------------------------
// Kernel 1: exact KNN. One 11-bit-histogram pass + exact ranking of the
// boundary bucket (reproduces top_k smallest-index tie-break).
// one block per query point, 256 threads. Spread shared atomics.
// ---------------------------------------------------------------------------
__global__ void knn_kernel(const int* __restrict__ knnp,
                           int* __restrict__ idx_out)
{
    __shared__ unsigned s_u[NN];          // 8 KB: sortable keys
    __shared__ int      s_hist[2048];     // 8 KB: 11-bit histogram, reused as cand list
    __shared__ int      s_wsum[8];
    __shared__ int      s_bucket, s_less, s_cnt, s_c;

    const int g    = blockIdx.x;          // 0..BN-1
    const int base = (g / NN) * NN;       // batch base
    const int tid  = threadIdx.x;
    const int lane = tid & 31;
    const int w    = tid >> 5;
    const int K    = *knnp;
    const unsigned FULL = 0xFFFFFFFFu;

    const float4 q = g_xyz4[g];
    const float xq = q.x, yq = q.y, zq = q.z, d2q = q.w;

    for (int i = tid; i < 2048; i += 256) s_hist[i] = 0;
    if (tid == 0) { s_cnt = 0; s_c = 0; }
    __syncthreads();

    // distances -> sortable uint keys + 11-bit histogram (spread atomics)
    for (int j = tid; j < NN; j += 256) {   // NN % 256 == 0: all lanes active
        const float4 p = g_xyz4[base + j];
        const float dt = fmaf(p.x, xq, fmaf(p.y, yq, p.z * zq));
        const float dist = (d2q + p.w) - 2.0f * dt;   // reference formula
        const unsigned bits = __float_as_uint(dist);
        const unsigned u = (bits & 0x80000000u) ? ~bits : (bits | 0x80000000u);
        s_u[j] = u;
        atomicAdd(&s_hist[u >> 21], 1);
    }
    __syncthreads();

    // find bucket containing rank K: thread t owns bins [8t, 8t+8)
    const int lo = tid * 8;
    int h[8]; int lsum = 0;
    #pragma unroll
    for (int i = 0; i < 8; ++i) { h[i] = s_hist[lo + i]; lsum += h[i]; }
    int incl = lsum;
    #pragma unroll
    for (int o = 1; o < 32; o <<= 1) {
        const int v = __shfl_up_sync(FULL, incl, o);
        if (lane >= o) incl += v;
    }
    if (lane == 31) s_wsum[w] = incl;
    __syncthreads();
    int woff = 0;
    #pragma unroll
    for (int i = 0; i < 8; ++i) if (i < w) woff += s_wsum[i];
    const int texcl = woff + incl - lsum;      // exclusive prefix for this thread's bins
    if (texcl < K && K <= woff + incl) {
        int cum = texcl;
        #pragma unroll
        for (int i = 0; i < 8; ++i) {
            if (cum + h[i] >= K) { s_bucket = lo + i; s_less = cum; break; }
            cum += h[i];
        }
    }
    __syncthreads();
    const unsigned B  = (unsigned)s_bucket;
    const int less    = s_less;
    const int rneed   = K - less;
    int* s_cand = s_hist;                     // histogram no longer needed

    // emit all strictly-smaller buckets (order-free, sparse predicate ->
    // plain atomics), compact boundary bucket candidates
    for (int j = tid; j < NN; j += 256) {
        const unsigned u = s_u[j];
        const unsigned bk = u >> 21;
        if (bk < B) {
            const int p = atomicAdd(&s_cnt, 1);
            idx_out[(size_t)g*KMAX + p] = base + j;
        } else if (bk == B) {
            const int p = atomicAdd(&s_c, 1);
            s_cand[p] = j;
        }
    }
    __syncthreads();

    // exact rank (value, then index) within boundary bucket -> positions [less, K)
    const int c = s_c;
    for (int ci = tid; ci < c; ci += 256) {
        const int j = s_cand[ci];
        const unsigned u = s_u[j];
        int rank = 0;
        for (int i = 0; i < c; ++i) {
            const int ji = s_cand[i];
            const unsigned ui = s_u[ji];
            rank += (ui < u) || (ui == u && ji < j);
        }
        if (rank < rneed)
            idx_out[(size_t)g*KMAX + less + rank] = base + j;
    }
}

// ---------------------------------------------------------------------------
// Kernel 2: A = pre @ W_r1 ; c = pre @ (W_r2 - W_r1) + b_r  (fp32 accumulate,
// fp16 store, oct layout). + fused v = relu(pre @ W_v + b_v) on y==0 blocks.
// tile 32 points x 128 cols, 256 threads, 4pt x 4col per thread
// ---------------------------------------------------------------------------
__global__ void prep_kernel(const float* __restrict__ feature,
                            const float* __restrict__ xyz,
                            const float* __restrict__ W_r,
                            const float* __restrict__ b_r,
                            const float* __restrict__ W_v,
                            const float* __restrict__ b_v)
{
    __shared__ float s_pre[PTS][CP3 + 1];
    __shared__ float s_w1[CP3][128];
    __shared__ float s_wd[CP3][128];

    const int p0  = blockIdx.x * PTS;
    const int c0  = blockIdx.y * 128;
    const int tid = threadIdx.x;

    for (int t = tid; t < PTS * CP3; t += 256) {
        const int p = t / CP3, i = t % CP3;
        const int gg = p0 + p;
        s_pre[p][i] = (i < CC) ? feature[(size_t)gg*CC + i] : xyz[(size_t)gg*3 + (i - CC)];
    }
    for (int t = tid; t < CP3 * 128; t += 256) {
        const int i = t >> 7, cc = t & 127;
        const float w1 = W_r[(size_t)i*DD2 + c0 + cc];
        const float w2 = W_r[(size_t)(CP3 + i)*DD2 + c0 + cc];
        s_w1[i][cc] = w1;
        s_wd[i][cc] = w2 - w1;
    }
    __syncthreads();

    const int cq  = tid & 31;        // col group (4 cols)
    const int prg = tid >> 5;        // point group: points prg + pp*8
    const int cb  = cq * 4;

    float accA[4][4] = {};
    float accC[4][4] = {};

    for (int i = 0; i < CP3; ++i) {
        const float4 w1 = *reinterpret_cast<const float4*>(&s_w1[i][cb]);
        const float4 wd = *reinterpret_cast<const float4*>(&s_wd[i][cb]);
        #pragma unroll
        for (int pp = 0; pp < 4; ++pp) {
            const float pv = s_pre[prg + pp*8][i];   // warp-uniform -> broadcast
            accA[pp][0] = fmaf(pv, w1.x, accA[pp][0]);
            accA[pp][1] = fmaf(pv, w1.y, accA[pp][1]);
            accA[pp][2] = fmaf(pv, w1.z, accA[pp][2]);
            accA[pp][3] = fmaf(pv, w1.w, accA[pp][3]);
            accC[pp][0] = fmaf(pv, wd.x, accC[pp][0]);
            accC[pp][1] = fmaf(pv, wd.y, accC[pp][1]);
            accC[pp][2] = fmaf(pv, wd.z, accC[pp][2]);
            accC[pp][3] = fmaf(pv, wd.w, accC[pp][3]);
        }
    }

    // oct-layout destination: col = d*32 + e ; flat = (e>>3)*256 + d*8 + (e&7)
    const int col0  = c0 + cb;              // multiple of 4
    const int dRow  = col0 >> 5;
    const int eBase = col0 & 31;            // multiple of 4
    const int qoff  = (eBase >> 3) * 256 + dRow * 8 + (eBase & 7);

    const float br0 = __ldg(b_r + col0 + 0), br1 = __ldg(b_r + col0 + 1);
    const float br2 = __ldg(b_r + col0 + 2), br3 = __ldg(b_r + col0 + 3);

    #pragma unroll
    for (int pp = 0; pp < 4; ++pp) {
        const int gg = p0 + prg + pp * 8;
        const size_t off = (size_t)gg * DD2 + qoff;
        *reinterpret_cast<__half2*>(&g_A[off])     = __floats2half2_rn(accA[pp][0], accA[pp][1]);
        *reinterpret_cast<__half2*>(&g_A[off + 2]) = __floats2half2_rn(accA[pp][2], accA[pp][3]);
        *reinterpret_cast<__half2*>(&g_c[off])     = __floats2half2_rn(accC[pp][0] + br0, accC[pp][1] + br1);
        *reinterpret_cast<__half2*>(&g_c[off + 2]) = __floats2half2_rn(accC[pp][2] + br2, accC[pp][3] + br3);
    }

    // fused v = relu(pre @ W_v + b_v) using the staged s_pre
    if (blockIdx.y == 0) {
        for (int t = tid; t < PTS * DD; t += 256) {
            const int p = t >> 5, d = t & 31;
            float acc = __ldg(b_v + d);
            #pragma unroll 7
            for (int i = 0; i < CP3; ++i)
                acc = fmaf(s_pre[p][i], __ldg(W_v + i*DD + d), acc);
            g_v[(size_t)(p0 + p)*DD + d] = fmaxf(acc, 0.0f);
        }
    }
}

// ---------------------------------------------------------------------------
// Kernel 3: main aggregation, split-row half2 pipeline, fp32 register
// accumulation (no per-k smem traffic), uint4 A/c loads, fused tail write.
// 256 threads = 8 warps = 2 points. Per point: 2 k-units x 2 d-half warps.
// lane = eh*16 + dp: thread owns row d = dhalf*16+dp, e in [eh*16, eh*16+16).
// hacc (half2) flushed into fp32 registers every 3 k (identical arithmetic
// to the smem version). Epilogue: one smem stage (scalar stores, pitch 33).
// ---------------------------------------------------------------------------
__global__ void __launch_bounds__(256)
main_kernel(const int* __restrict__ knnp,
            const float* __restrict__ W_s,
            const float* __restrict__ b_s,
            float* __restrict__ out,
            int tailpos)
{
    __shared__ float s_acc[8][16][33];    // epilogue staging only (16.5 KB)

    const int tid   = threadIdx.x;
    const int lane  = tid & 31;
    const int w     = tid >> 5;
    const int pw    = w >> 2;             // point within block (0/1)
    const int wq    = w & 3;              // warp within point
    const int unit  = wq >> 1;            // k-parity unit (0/1)
    const int dhalf = wq & 1;             // which 16 rows
    const int dp    = lane & 15;
    const int eh    = lane >> 4;          // which 16 cols
    const int d     = dhalf * 16 + dp;
    const int g     = blockIdx.x * 2 + pw;
    const int K     = *knnp;

    if (tailpos >= 0 && blockIdx.x == 0 && tid == 255)
        out[tailpos] = (float)NN;

    // c half-row: two uint4 at index (eh*2+q)*32 + d
    const uint4* __restrict__ Cq = reinterpret_cast<const uint4*>(g_c + (size_t)g * DD2);
    const int li0 = (eh*2    )*32 + d;
    const int li1 = (eh*2 + 1)*32 + d;
    __half2 ch[8];
    {
        const uint4 c0v = Cq[li0];
        const uint4 c1v = Cq[li1];
        ch[0] = *reinterpret_cast<const __half2*>(&c0v.x);
        ch[1] = *reinterpret_cast<const __half2*>(&c0v.y);
        ch[2] = *reinterpret_cast<const __half2*>(&c0v.z);
        ch[3] = *reinterpret_cast<const __half2*>(&c0v.w);
        ch[4] = *reinterpret_cast<const __half2*>(&c1v.x);
        ch[5] = *reinterpret_cast<const __half2*>(&c1v.y);
        ch[6] = *reinterpret_cast<const __half2*>(&c1v.z);
        ch[7] = *reinterpret_cast<const __half2*>(&c1v.w);
    }

    float acc[16];
    #pragma unroll
    for (int i = 0; i < 16; ++i) acc[i] = 0.0f;

    const int* __restrict__ idxp = g_idx + (size_t)g * KMAX;
    const float SQRTD = 5.656854249492381f;   // sqrt(32)
    const __half2 HZ = __float2half2_rn(0.0f);

    int k = unit;
    #pragma unroll 1
    while (k < K) {
        __half2 hacc[8];
        #pragma unroll
        for (int i = 0; i < 8; ++i) hacc[i] = HZ;

        #pragma unroll 1
        for (int t = 0; t < 3 && k < K; ++t, k += 2) {
            const int m = __ldg(idxp + k);
            const uint4* __restrict__ Aq =
                reinterpret_cast<const uint4*>(g_A + (size_t)m * DD2);
            const float gvv = __ldg(g_v + (size_t)m*DD + d);

            const uint4 r0 = Aq[li0];
            const uint4 r1 = Aq[li1];

            __half2 xh[8];
            __half2 rsh = HZ;
            xh[0] = __hadd2(*reinterpret_cast<const __half2*>(&r0.x), ch[0]);
            xh[1] = __hadd2(*reinterpret_cast<const __half2*>(&r0.y), ch[1]);
            xh[2] = __hadd2(*reinterpret_cast<const __half2*>(&r0.z), ch[2]);
            xh[3] = __hadd2(*reinterpret_cast<const __half2*>(&r0.w), ch[3]);
            xh[4] = __hadd2(*reinterpret_cast<const __half2*>(&r1.x), ch[4]);
            xh[5] = __hadd2(*reinterpret_cast<const __half2*>(&r1.y), ch[5]);
            xh[6] = __hadd2(*reinterpret_cast<const __half2*>(&r1.z), ch[6]);
            xh[7] = __hadd2(*reinterpret_cast<const __half2*>(&r1.w), ch[7]);
            #pragma unroll
            for (int i = 0; i < 8; ++i)
                rsh = __hadd2(rsh, __habs2(xh[i]));

            const float2 fr = __half22float2(rsh);
            float rs = fr.x + fr.y;
            rs += __shfl_xor_sync(0xFFFFFFFFu, rs, 16);     // full row sum
            const float coef = gvv * __fdividef(SQRTD, rs + 3.2e-6f);  // + D*1e-7
            const __half2 c2 = __float2half2_rn(coef);

            #pragma unroll
            for (int i = 0; i < 8; ++i)
                hacc[i] = __hfma2(c2, xh[i], hacc[i]);
        }

        // flush half partials into fp32 registers (identical arithmetic)
        #pragma unroll
        for (int i = 0; i < 8; ++i) {
            const float2 f = __half22float2(hacc[i]);
            acc[i*2]     += f.x;
            acc[i*2 + 1] += f.y;
        }
    }

    // stage: thread's 16 e-values (scalar stores — pitch 33 is 4B-aligned only)
    #pragma unroll
    for (int j = 0; j < 16; ++j)
        s_acc[w][dp][eh*16 + j] = acc[j];
    __syncthreads();

    // epilogue: sum the point's 4 warp regions over all 16 dp rows, then W_s
    if (wq == 0) {
        const int b0 = pw * 4;
        float tot = 0.0f;
        #pragma unroll
        for (int dd = 0; dd < 16; ++dd)
            tot += (s_acc[b0][dd][lane]   + s_acc[b0+1][dd][lane])
                 + (s_acc[b0+2][dd][lane] + s_acc[b0+3][dd][lane]);
        float o2 = b_s[lane];
        #pragma unroll
        for (int e = 0; e < DD; ++e) {
            const float te = __shfl_sync(0xFFFFFFFFu, tot, e);
            o2 = fmaf(te, W_s[e*DD + lane], o2);
        }
        out[(size_t)g*DD + lane] = o2;
    }
}

// ---------------------------------------------------------------------------
// Side stream + events for graph-forked knn/prep overlap.
// ---------------------------------------------------------------------------
static cudaStream_t g_s1 = nullptr;
static cudaEvent_t  g_evFork = nullptr, g_evJoin = nullptr;

extern "C" void kernel_launch(void* const* d_in, const int* in_sizes, int n_in,
                              void* d_out, int out_size)
{
    const float* feature = (const float*)d_in[0];
    const float* xyz     = (const float*)d_in[1];
    const float* W_r     = (const float*)d_in[2];
    const float* b_r     = (const float*)d_in[3];
    const float* W_v     = (const float*)d_in[4];
    const float* b_v     = (const float*)d_in[5];
    const float* W_s     = (const float*)d_in[6];
    const float* b_s     = (const float*)d_in[7];
    const int*   knnp    = (const int*)d_in[8];
    float* out = (float*)d_out;

    int* idx_out;
    cudaGetSymbolAddress((void**)&idx_out, g_idx);  // host-side address query (no alloc)

    if (g_s1 == nullptr) {
        cudaStreamCreateWithFlags(&g_s1, cudaStreamNonBlocking);
        cudaEventCreateWithFlags(&g_evFork, cudaEventDisableTiming);
        cudaEventCreateWithFlags(&g_evJoin, cudaEventDisableTiming);
    }

    // pack xyz (+|p|^2) first; knn (side stream) depends on it via fork event
    pack_kernel<<<(BN + 255)/256, 256>>>(xyz);
    cudaEventRecord(g_evFork, 0);
    cudaStreamWaitEvent(g_s1, g_evFork, 0);
    knn_kernel<<<BN, 256, 0, g_s1>>>(knnp, idx_out);
    prep_kernel<<<dim3(BN/PTS, DD2/128), 256>>>(feature, xyz, W_r, b_r, W_v, b_v);
    // join: main needs both
    cudaEventRecord(g_evJoin, g_s1);
    cudaStreamWaitEvent(0, g_evJoin, 0);

    const int total = BN * DD;
    const int tailpos = (out_size > total) ? total : -1;
    main_kernel<<<BN/2, 256>>>(knnp, W_s, b_s, out, tailpos);
}